// round 15
// baseline (speedup 1.0000x reference)
#include <cuda_runtime.h>
#include <cuda_fp16.h>
#include <cstdint>

#define BATCH 2
#define C 256
#define NPOS 4096
#define CN ((size_t)C * NPOS)
#define SN ((size_t)NPOS * NPOS)

// ---------------- scratch (static device globals) ---------------------------
__device__ __align__(16) __half g_h[BATCH * NPOS * C];   // gn out, position-major
__device__ __align__(16) __half g_w[4 * C * C];          // weights fp16
__device__ __align__(16) __half g_q[BATCH * NPOS * C];   // position-major
__device__ __align__(16) __half g_k[BATCH * NPOS * C];
__device__ __align__(16) __half g_v[BATCH * C * NPOS];   // channel-major
__device__ __align__(16) __half g_p[BATCH * SN];         // P' = exp(S), fp16 (67 MB)
__device__ __align__(16) __half g_o[BATCH * NPOS * C];   // attn out, position-major
__device__ float g_rsum[BATCH * NPOS];                   // row sums of P'
__device__ float g_stats[BATCH * 32 * 2];

// ---------------- PTX primitives ---------------------------------------------
__device__ __forceinline__ uint32_t smem_u32(const void* p) {
    uint32_t r;
    asm("{ .reg .u64 t; cvta.to.shared.u64 t, %1; cvt.u32.u64 %0, t; }" : "=r"(r) : "l"(p));
    return r;
}
__device__ __forceinline__ void cpasync16(uint32_t s, const void* g) {
    asm volatile("cp.async.cg.shared.global [%0], [%1], 16;" :: "r"(s), "l"(g) : "memory");
}
__device__ __forceinline__ void cp_commit() {
    asm volatile("cp.async.commit_group;" ::: "memory");
}
__device__ __forceinline__ void cp_wait0() {
    asm volatile("cp.async.wait_group 0;" ::: "memory");
}
__device__ __forceinline__ void ldsm4(uint32_t (&r)[4], uint32_t addr) {
    asm volatile("ldmatrix.sync.aligned.m8n8.x4.shared.b16 {%0,%1,%2,%3}, [%4];"
                 : "=r"(r[0]), "=r"(r[1]), "=r"(r[2]), "=r"(r[3]) : "r"(addr));
}
__device__ __forceinline__ void mma16816(float (&c)[4], const uint32_t (&a)[4],
                                         uint32_t b0, uint32_t b1) {
    asm volatile(
        "mma.sync.aligned.m16n8k16.row.col.f32.f16.f16.f32 "
        "{%0,%1,%2,%3}, {%4,%5,%6,%7}, {%8,%9}, {%0,%1,%2,%3};"
        : "+f"(c[0]), "+f"(c[1]), "+f"(c[2]), "+f"(c[3])
        : "r"(a[0]), "r"(a[1]), "r"(a[2]), "r"(a[3]), "r"(b0), "r"(b1));
}

// ---------------- main GEMM core: CTA 128x128, 8 warps 64x32, K-chunk 64 -----
#define ROWB 144
#define SM_B_OFF 18432                 // 128*144
#define STAGE_SZ 36864
#define SMEM_BYTES (2 * STAGE_SZ)      // 73728

__device__ __forceinline__ void issue_chunk(uint32_t sb, const __half* A, int lda,
                                            const __half* B, int ldb, int k0) {
    const int t = threadIdx.x;
    #pragma unroll
    for (int i = 0; i < 4; ++i) {
        int v = t + (i << 8);
        int row = v >> 3, seg = v & 7;
        cpasync16(sb + row * ROWB + (seg << 4), A + (size_t)row * lda + k0 + (seg << 3));
    }
    #pragma unroll
    for (int i = 0; i < 4; ++i) {
        int v = t + (i << 8);
        int row = v >> 3, seg = v & 7;
        cpasync16(sb + SM_B_OFF + row * ROWB + (seg << 4),
                  B + (size_t)row * ldb + k0 + (seg << 3));
    }
}

__device__ __forceinline__ void compute_chunk(uint32_t s, float acc[4][4][4]) {
    const int lane = threadIdx.x & 31, wid = threadIdx.x >> 5;
    const int m0w = (wid & 1) << 6;
    const int n0w = (wid >> 1) << 5;
    const int arow = lane & 15;
    const int khalf = (lane >> 4) << 3;
    #pragma unroll
    for (int s16 = 0; s16 < 64; s16 += 16) {
        const int coff = (s16 + khalf) * 2;
        uint32_t a[4][4], b[2][4];
        #pragma unroll
        for (int mi = 0; mi < 4; ++mi)
            ldsm4(a[mi], s + (m0w + mi * 16 + arow) * ROWB + coff);
        #pragma unroll
        for (int nj = 0; nj < 2; ++nj)
            ldsm4(b[nj], s + SM_B_OFF + (n0w + nj * 16 + arow) * ROWB + coff);
        #pragma unroll
        for (int mi = 0; mi < 4; ++mi)
            #pragma unroll
            for (int ni = 0; ni < 4; ++ni) {
                const int nj = ni >> 1, sel = ni & 1;
                mma16816(acc[mi][ni], a[mi], b[nj][sel], b[nj][sel + 2]);
            }
    }
}

__device__ __forceinline__ void gemm_run(uint32_t sb, const __half* A, int lda,
                                         const __half* B, int ldb, int K,
                                         float acc[4][4][4]) {
    #pragma unroll
    for (int mi = 0; mi < 4; ++mi)
        #pragma unroll
        for (int ni = 0; ni < 4; ++ni)
            #pragma unroll
            for (int r = 0; r < 4; ++r) acc[mi][ni][r] = 0.f;

    const int nc = K >> 6;
    issue_chunk(sb, A, lda, B, ldb, 0);
    cp_commit();
    for (int c = 0; c < nc; ++c) {
        cp_wait0();
        __syncthreads();
        if (c + 1 < nc) {
            issue_chunk(sb + ((c + 1) & 1) * STAGE_SZ, A, lda, B, ldb, (c + 1) << 6);
            cp_commit();
        }
        compute_chunk(sb + (c & 1) * STAGE_SZ, acc);
    }
}

#define EPI_COORDS                                     \
    const int lane = threadIdx.x & 31;                 \
    const int wid = threadIdx.x >> 5;                  \
    const int mw = (wid & 1) << 6;                     \
    const int nw = (wid >> 1) << 5;                    \
    const int r0 = lane >> 2;                          \
    const int c0 = (lane & 3) << 1;

// ---- narrow PIPELINED core: CTA 128x64, 8 warps 32x32, K-chunk 64,
//      fragment double-buffering (load step s+1 frags under step s mma) --------
#define STAGE64 27648                  // A 128*144 + B 64*144

__device__ __forceinline__ void issue_chunk64(uint32_t sb, const __half* A, int lda,
                                              const __half* B, int ldb, int k0) {
    const int t = threadIdx.x;
    #pragma unroll
    for (int i = 0; i < 4; ++i) {
        int v = t + (i << 8);
        int row = v >> 3, seg = v & 7;
        cpasync16(sb + row * ROWB + (seg << 4), A + (size_t)row * lda + k0 + (seg << 3));
    }
    #pragma unroll
    for (int i = 0; i < 2; ++i) {
        int v = t + (i << 8);
        int row = v >> 3, seg = v & 7;
        cpasync16(sb + SM_B_OFF + row * ROWB + (seg << 4),
                  B + (size_t)row * ldb + k0 + (seg << 3));
    }
}

__device__ __forceinline__ void ld_frags64(uint32_t s, int coff,
                                           uint32_t (&a)[2][4], uint32_t (&b)[2][4],
                                           int m0w, int n0w, int arow) {
    #pragma unroll
    for (int mi = 0; mi < 2; ++mi)
        ldsm4(a[mi], s + (m0w + mi * 16 + arow) * ROWB + coff);
    #pragma unroll
    for (int nj = 0; nj < 2; ++nj)
        ldsm4(b[nj], s + SM_B_OFF + (n0w + nj * 16 + arow) * ROWB + coff);
}

__device__ __forceinline__ void compute_chunk64p(uint32_t s, float acc[2][4][4]) {
    const int lane = threadIdx.x & 31, wid = threadIdx.x >> 5;
    const int m0w = (wid & 3) << 5;      // 0,32,64,96
    const int n0w = (wid >> 2) << 5;     // 0,32
    const int arow = lane & 15;
    const int khalf = (lane >> 4) << 3;
    uint32_t a[2][2][4], b[2][2][4];

    ld_frags64(s, khalf * 2, a[0], b[0], m0w, n0w, arow);
    #pragma unroll
    for (int st = 0; st < 4; ++st) {
        const int cur = st & 1;
        if (st < 3)
            ld_frags64(s, ((st + 1) * 16 + khalf) * 2, a[cur ^ 1], b[cur ^ 1],
                       m0w, n0w, arow);
        #pragma unroll
        for (int mi = 0; mi < 2; ++mi)
            #pragma unroll
            for (int ni = 0; ni < 4; ++ni) {
                const int nj = ni >> 1, sel = ni & 1;
                mma16816(acc[mi][ni], a[cur][mi], b[cur][nj][sel], b[cur][nj][sel + 2]);
            }
    }
}

__device__ __forceinline__ void gemm_run64p(uint32_t sb, const __half* A, int lda,
                                            const __half* B, int ldb, int K,
                                            float acc[2][4][4]) {
    #pragma unroll
    for (int mi = 0; mi < 2; ++mi)
        #pragma unroll
        for (int ni = 0; ni < 4; ++ni)
            #pragma unroll
            for (int r = 0; r < 4; ++r) acc[mi][ni][r] = 0.f;

    const int nc = K >> 6;
    issue_chunk64(sb, A, lda, B, ldb, 0);
    cp_commit();
    for (int c = 0; c < nc; ++c) {
        cp_wait0();
        __syncthreads();
        if (c + 1 < nc) {
            issue_chunk64(sb + ((c + 1) & 1) * STAGE64, A, lda, B, ldb, (c + 1) << 6);
            cp_commit();
        }
        compute_chunk64p(sb + (c & 1) * STAGE64, acc);
    }
}

#define EPI_COORDS64                                   \
    const int lane = threadIdx.x & 31;                 \
    const int wid = threadIdx.x >> 5;                  \
    const int mw = (wid & 3) << 5;                     \
    const int nw = (wid >> 2) << 5;                    \
    const int r0 = lane >> 2;                          \
    const int c0 = (lane & 3) << 1;

// ---------------- prep kernels ------------------------------------------------
__global__ void __launch_bounds__(256) conv_w_kernel(
        const float* __restrict__ wq, const float* __restrict__ wk,
        const float* __restrict__ wv, const float* __restrict__ wp) {
    int i = blockIdx.x * 256 + threadIdx.x;
    int which = i >> 16, j = i & 65535;
    const float* w = which == 0 ? wq : (which == 1 ? wk : (which == 2 ? wv : wp));
    g_w[i] = __float2half(w[j]);
}

__global__ void __launch_bounds__(256) gn_stats_kernel(const float* __restrict__ x) {
    if (threadIdx.x < 128) g_rsum[blockIdx.x * 128 + threadIdx.x] = 0.f;

    int b = blockIdx.x >> 5, g = blockIdx.x & 31;
    const size_t base = ((size_t)b * C + g * 8) * NPOS;
    const float4* xp = (const float4*)(x + base);
    const int NV = 8 * NPOS / 4;
    float s = 0.f, ss = 0.f;
    for (int i = threadIdx.x; i < NV; i += 256) {
        float4 v = xp[i];
        s  += v.x + v.y + v.z + v.w;
        ss += v.x * v.x + v.y * v.y + v.z * v.z + v.w * v.w;
    }
    #pragma unroll
    for (int o = 16; o; o >>= 1) {
        s  += __shfl_xor_sync(0xffffffffu, s, o);
        ss += __shfl_xor_sync(0xffffffffu, ss, o);
    }
    __shared__ float shs[8], shss[8];
    int w = threadIdx.x >> 5;
    if ((threadIdx.x & 31) == 0) { shs[w] = s; shss[w] = ss; }
    __syncthreads();
    if (threadIdx.x == 0) {
        float ts = 0.f, tss = 0.f;
        #pragma unroll
        for (int i = 0; i < 8; ++i) { ts += shs[i]; tss += shss[i]; }
        const float invN = 1.f / (8 * NPOS);
        float mean = ts * invN;
        float var = tss * invN - mean * mean;
        g_stats[blockIdx.x * 2]     = mean;
        g_stats[blockIdx.x * 2 + 1] = rsqrtf(var + 1e-6f);
    }
}

__global__ void gn_apply_kernel(const float* __restrict__ x,
                                const float* __restrict__ gamma,
                                const float* __restrict__ beta) {
    __shared__ float tile[32][33];
    int b = blockIdx.z, c0b = blockIdx.y * 32, n0b = blockIdx.x * 32;
    int tx = threadIdx.x, ty = threadIdx.y;
    #pragma unroll
    for (int i = 0; i < 4; ++i) {
        int cl = ty + i * 8;
        int c = c0b + cl;
        int g = c >> 3;
        float mean = g_stats[(b * 32 + g) * 2];
        float inv  = g_stats[(b * 32 + g) * 2 + 1];
        float gmul = gamma[c] * inv;
        float gadd = beta[c] - mean * gmul;
        float v = x[((size_t)b * C + c) * NPOS + n0b + tx];
        tile[cl][tx] = v * gmul + gadd;
    }
    __syncthreads();
    #pragma unroll
    for (int i = 0; i < 4; ++i) {
        int nl = ty + i * 8;
        size_t o = ((size_t)b * NPOS + n0b + nl) * C + c0b + tx;
        g_h[o] = __float2half(tile[tx][nl]);
    }
}

// ---------------- merged QKV kernel (flattened grid, 384 CTAs) ----------------
__global__ void __launch_bounds__(256, 2) qkv_gemm(const float* __restrict__ bq,
                                                   const float* __restrict__ bk,
                                                   const float* __restrict__ bv) {
    extern __shared__ char smem[];
    uint32_t sb = smem_u32(smem);
    int t = blockIdx.x;
    float acc[4][4][4];

    if (t < 256) {
        int which = t >> 7, r = t & 127;
        int b = r >> 6;
        int m0 = ((r & 63) >> 1) * 128;   // positions
        int n0 = (r & 1) * 128;           // out channels
        const __half* A = g_h + ((size_t)b * NPOS + m0) * C;
        const __half* B = g_w + (size_t)which * C * C + (size_t)n0 * C;
        gemm_run(sb, A, C, B, C, C, acc);

        const float* bias = which == 0 ? bq : bk;
        __half* out = which == 0 ? g_q : g_k;
        EPI_COORDS;
        #pragma unroll
        for (int ni = 0; ni < 4; ++ni) {
            int colg = n0 + nw + ni * 8 + c0;
            float bb0 = bias[colg], bb1 = bias[colg + 1];
            #pragma unroll
            for (int mi = 0; mi < 4; ++mi)
                #pragma unroll
                for (int rr = 0; rr < 2; ++rr) {
                    int rowg = m0 + mw + mi * 16 + r0 + rr * 8;
                    size_t off = ((size_t)b * NPOS + rowg) * C + colg;
                    *reinterpret_cast<__half2*>(out + off) =
                        __floats2half2_rn(acc[mi][ni][rr * 2] + bb0,
                                          acc[mi][ni][rr * 2 + 1] + bb1);
                }
        }
    } else {
        int r = t - 256;
        int b = r >> 6;
        int m0 = ((r & 63) & 1) * 128;    // channels
        int n0 = ((r & 63) >> 1) * 128;   // positions
        const __half* A = g_w + (size_t)2 * C * C + (size_t)m0 * C;
        const __half* B = g_h + ((size_t)b * NPOS + n0) * C;
        gemm_run(sb, A, C, B, C, C, acc);

        EPI_COORDS;
        #pragma unroll
        for (int mi = 0; mi < 4; ++mi)
            #pragma unroll
            for (int rr = 0; rr < 2; ++rr) {
                int rowg = m0 + mw + mi * 16 + r0 + rr * 8;
                float bb = bv[rowg];
                #pragma unroll
                for (int ni = 0; ni < 4; ++ni) {
                    int colg = n0 + nw + ni * 8 + c0;
                    size_t off = (size_t)b * CN + (size_t)rowg * NPOS + colg;
                    *reinterpret_cast<__half2*>(g_v + off) =
                        __floats2half2_rn(acc[mi][ni][rr * 2] + bb,
                                          acc[mi][ni][rr * 2 + 1] + bb);
                }
            }
    }
}

// S+exp: P'[i,j] = exp(1/16 * Q[i,:].K[j,:]^T) fp16; row sums -> g_rsum.
// CTA tile 128(i) x 64(j), pipelined narrow core. (no max subtraction: |S|<~6)
__global__ void __launch_bounds__(256, 2) s_gemm() {
    extern __shared__ char smem[];
    uint32_t sb = smem_u32(smem);
    int b = blockIdx.z;
    int m0 = blockIdx.y * 128, n0 = blockIdx.x * 64;
    const __half* A = g_q + ((size_t)b * NPOS + m0) * C;
    const __half* B = g_k + ((size_t)b * NPOS + n0) * C;
    float acc[2][4][4];
    gemm_run64p(sb, A, C, B, C, C, acc);

    __shared__ float srows[128];
    if (threadIdx.x < 128) srows[threadIdx.x] = 0.f;
    __syncthreads();

    EPI_COORDS64;
    __half* S = g_p + (size_t)b * SN;
    #pragma unroll
    for (int mi = 0; mi < 2; ++mi)
        #pragma unroll
        for (int rr = 0; rr < 2; ++rr) {
            int rowl = mw + mi * 16 + r0 + rr * 8;
            int rowg = m0 + rowl;
            float part = 0.f;
            #pragma unroll
            for (int ni = 0; ni < 4; ++ni) {
                int colg = n0 + nw + ni * 8 + c0;
                float e0 = __expf(acc[mi][ni][rr * 2] * 0.0625f);
                float e1 = __expf(acc[mi][ni][rr * 2 + 1] * 0.0625f);
                part += e0 + e1;
                *reinterpret_cast<__half2*>(S + (size_t)rowg * NPOS + colg) =
                    __floats2half2_rn(e0, e1);
            }
            part += __shfl_xor_sync(0xffffffffu, part, 1);
            part += __shfl_xor_sync(0xffffffffu, part, 2);
            if ((lane & 3) == 0) atomicAdd(&srows[rowl], part);
        }
    __syncthreads();
    if (threadIdx.x < 128)
        atomicAdd(&g_rsum[(size_t)b * NPOS + m0 + threadIdx.x], srows[threadIdx.x]);
}

// AV: O[i, c] = (P'[i,:] . V[c,:]^T) / rsum[i]  (K = 4096). CTA tile 128x64.
__global__ void __launch_bounds__(256, 2) av_gemm() {
    extern __shared__ char smem[];
    uint32_t sb = smem_u32(smem);
    int b = blockIdx.z;
    int m0 = blockIdx.y * 128, n0 = blockIdx.x * 64;
    const __half* A = g_p + (size_t)b * SN + (size_t)m0 * NPOS;
    const __half* B = g_v + (size_t)b * CN + (size_t)n0 * NPOS;
    float acc[2][4][4];
    gemm_run64p(sb, A, NPOS, B, NPOS, NPOS, acc);

    EPI_COORDS64;
    #pragma unroll
    for (int mi = 0; mi < 2; ++mi)
        #pragma unroll
        for (int rr = 0; rr < 2; ++rr) {
            int rowg = m0 + mw + mi * 16 + r0 + rr * 8;
            float inv = 1.f / g_rsum[(size_t)b * NPOS + rowg];
            #pragma unroll
            for (int ni = 0; ni < 4; ++ni) {
                int colg = n0 + nw + ni * 8 + c0;
                size_t off = ((size_t)b * NPOS + rowg) * C + colg;
                *reinterpret_cast<__half2*>(g_o + off) =
                    __floats2half2_rn(acc[mi][ni][rr * 2] * inv,
                                      acc[mi][ni][rr * 2 + 1] * inv);
            }
        }
}

// proj: out[c, n] = x[c, n] + Wp[c,:] . O[n,:]^T + bp[c]. CTA tile 128x64.
__global__ void __launch_bounds__(256, 2) proj_gemm(const float* __restrict__ bp,
                                                    const float* __restrict__ x,
                                                    float* __restrict__ out) {
    extern __shared__ char smem[];
    uint32_t sb = smem_u32(smem);
    int b = blockIdx.z;
    int m0 = blockIdx.y * 128, n0 = blockIdx.x * 64;
    const __half* A = g_w + (size_t)3 * C * C + (size_t)m0 * C;
    const __half* B = g_o + ((size_t)b * NPOS + n0) * C;
    float acc[2][4][4];
    gemm_run64p(sb, A, C, B, C, C, acc);

    EPI_COORDS64;
    #pragma unroll
    for (int mi = 0; mi < 2; ++mi)
        #pragma unroll
        for (int rr = 0; rr < 2; ++rr) {
            int rowg = m0 + mw + mi * 16 + r0 + rr * 8;
            float bb = bp[rowg];
            #pragma unroll
            for (int ni = 0; ni < 4; ++ni) {
                int colg = n0 + nw + ni * 8 + c0;
                size_t off = (size_t)b * CN + (size_t)rowg * NPOS + colg;
                float2 xv = *reinterpret_cast<const float2*>(x + off);
                float2 ov = make_float2(xv.x + acc[mi][ni][rr * 2] + bb,
                                        xv.y + acc[mi][ni][rr * 2 + 1] + bb);
                *reinterpret_cast<float2*>(out + off) = ov;
            }
        }
}

// ---------------- launch ------------------------------------------------------
extern "C" void kernel_launch(void* const* d_in, const int* in_sizes, int n_in,
                              void* d_out, int out_size) {
    const float* x  = (const float*)d_in[0];
    const float* gs = (const float*)d_in[1];
    const float* gb = (const float*)d_in[2];
    const float* wq = (const float*)d_in[3];
    const float* bq = (const float*)d_in[4];
    const float* wk = (const float*)d_in[5];
    const float* bk = (const float*)d_in[6];
    const float* wv = (const float*)d_in[7];
    const float* bv = (const float*)d_in[8];
    const float* wp = (const float*)d_in[9];
    const float* bp = (const float*)d_in[10];
    float* out = (float*)d_out;

    static bool attr_done = false;
    if (!attr_done) {
        cudaFuncSetAttribute(qkv_gemm,  cudaFuncAttributeMaxDynamicSharedMemorySize, SMEM_BYTES);
        cudaFuncSetAttribute(s_gemm,    cudaFuncAttributeMaxDynamicSharedMemorySize, 2 * STAGE64);
        cudaFuncSetAttribute(av_gemm,   cudaFuncAttributeMaxDynamicSharedMemorySize, 2 * STAGE64);
        cudaFuncSetAttribute(proj_gemm, cudaFuncAttributeMaxDynamicSharedMemorySize, 2 * STAGE64);
        attr_done = true;
    }

    conv_w_kernel<<<4 * C * C / 256, 256>>>(wq, wk, wv, wp);
    gn_stats_kernel<<<BATCH * 32, 256>>>(x);
    gn_apply_kernel<<<dim3(NPOS / 32, C / 32, BATCH), dim3(32, 8)>>>(x, gs, gb);
    qkv_gemm<<<384, 256, SMEM_BYTES>>>(bq, bk, bv);
    s_gemm<<<dim3(NPOS / 64, NPOS / 128, BATCH), 256, 2 * STAGE64>>>();
    av_gemm<<<dim3(C / 64, NPOS / 128, BATCH), 256, 2 * STAGE64>>>();
    proj_gemm<<<dim3(NPOS / 64, C / 128, BATCH), 256, 2 * STAGE64>>>(bp, x, out);
}

// round 16
// speedup vs baseline: 1.0722x; 1.0722x over previous
#include <cuda_runtime.h>
#include <cuda_fp16.h>
#include <cstdint>

#define BATCH 2
#define C 256
#define NPOS 4096
#define CN ((size_t)C * NPOS)
#define SN ((size_t)NPOS * NPOS)

// ---------------- scratch (static device globals) ---------------------------
__device__ __align__(16) __half g_h[BATCH * NPOS * C];   // gn out, position-major
__device__ __align__(16) __half g_w[4 * C * C];          // weights fp16
__device__ __align__(16) __half g_q[BATCH * NPOS * C];   // position-major
__device__ __align__(16) __half g_k[BATCH * NPOS * C];
__device__ __align__(16) __half g_v[BATCH * C * NPOS];   // channel-major
__device__ __align__(16) __half g_p[BATCH * SN];         // P' = exp(S), fp16 (67 MB)
__device__ __align__(16) __half g_o[BATCH * NPOS * C];   // attn out, position-major
__device__ float g_rsum[BATCH * NPOS];                   // row sums of P'
__device__ float g_stats[BATCH * 32 * 2];

// ---------------- PTX primitives ---------------------------------------------
__device__ __forceinline__ uint32_t smem_u32(const void* p) {
    uint32_t r;
    asm("{ .reg .u64 t; cvta.to.shared.u64 t, %1; cvt.u32.u64 %0, t; }" : "=r"(r) : "l"(p));
    return r;
}
__device__ __forceinline__ void cpasync16(uint32_t s, const void* g) {
    asm volatile("cp.async.cg.shared.global [%0], [%1], 16;" :: "r"(s), "l"(g) : "memory");
}
__device__ __forceinline__ void cp_commit() {
    asm volatile("cp.async.commit_group;" ::: "memory");
}
__device__ __forceinline__ void cp_wait0() {
    asm volatile("cp.async.wait_group 0;" ::: "memory");
}
__device__ __forceinline__ void ldsm4(uint32_t (&r)[4], uint32_t addr) {
    asm volatile("ldmatrix.sync.aligned.m8n8.x4.shared.b16 {%0,%1,%2,%3}, [%4];"
                 : "=r"(r[0]), "=r"(r[1]), "=r"(r[2]), "=r"(r[3]) : "r"(addr));
}
__device__ __forceinline__ void mma16816(float (&c)[4], const uint32_t (&a)[4],
                                         uint32_t b0, uint32_t b1) {
    asm volatile(
        "mma.sync.aligned.m16n8k16.row.col.f32.f16.f16.f32 "
        "{%0,%1,%2,%3}, {%4,%5,%6,%7}, {%8,%9}, {%0,%1,%2,%3};"
        : "+f"(c[0]), "+f"(c[1]), "+f"(c[2]), "+f"(c[3])
        : "r"(a[0]), "r"(a[1]), "r"(a[2]), "r"(a[3]), "r"(b0), "r"(b1));
}

// ---------------- main GEMM core: CTA 128x128, 8 warps 64x32, K-chunk 64 -----
#define ROWB 144
#define SM_B_OFF 18432                 // 128*144
#define STAGE_SZ 36864
#define SMEM_BYTES (2 * STAGE_SZ)      // 73728

__device__ __forceinline__ void issue_chunk(uint32_t sb, const __half* A, int lda,
                                            const __half* B, int ldb, int k0) {
    const int t = threadIdx.x;
    #pragma unroll
    for (int i = 0; i < 4; ++i) {
        int v = t + (i << 8);
        int row = v >> 3, seg = v & 7;
        cpasync16(sb + row * ROWB + (seg << 4), A + (size_t)row * lda + k0 + (seg << 3));
    }
    #pragma unroll
    for (int i = 0; i < 4; ++i) {
        int v = t + (i << 8);
        int row = v >> 3, seg = v & 7;
        cpasync16(sb + SM_B_OFF + row * ROWB + (seg << 4),
                  B + (size_t)row * ldb + k0 + (seg << 3));
    }
}

__device__ __forceinline__ void compute_chunk(uint32_t s, float acc[4][4][4]) {
    const int lane = threadIdx.x & 31, wid = threadIdx.x >> 5;
    const int m0w = (wid & 1) << 6;
    const int n0w = (wid >> 1) << 5;
    const int arow = lane & 15;
    const int khalf = (lane >> 4) << 3;
    #pragma unroll
    for (int s16 = 0; s16 < 64; s16 += 16) {
        const int coff = (s16 + khalf) * 2;
        uint32_t a[4][4], b[2][4];
        #pragma unroll
        for (int mi = 0; mi < 4; ++mi)
            ldsm4(a[mi], s + (m0w + mi * 16 + arow) * ROWB + coff);
        #pragma unroll
        for (int nj = 0; nj < 2; ++nj)
            ldsm4(b[nj], s + SM_B_OFF + (n0w + nj * 16 + arow) * ROWB + coff);
        #pragma unroll
        for (int mi = 0; mi < 4; ++mi)
            #pragma unroll
            for (int ni = 0; ni < 4; ++ni) {
                const int nj = ni >> 1, sel = ni & 1;
                mma16816(acc[mi][ni], a[mi], b[nj][sel], b[nj][sel + 2]);
            }
    }
}

__device__ __forceinline__ void gemm_run(uint32_t sb, const __half* A, int lda,
                                         const __half* B, int ldb, int K,
                                         float acc[4][4][4]) {
    #pragma unroll
    for (int mi = 0; mi < 4; ++mi)
        #pragma unroll
        for (int ni = 0; ni < 4; ++ni)
            #pragma unroll
            for (int r = 0; r < 4; ++r) acc[mi][ni][r] = 0.f;

    const int nc = K >> 6;
    issue_chunk(sb, A, lda, B, ldb, 0);
    cp_commit();
    for (int c = 0; c < nc; ++c) {
        cp_wait0();
        __syncthreads();
        if (c + 1 < nc) {
            issue_chunk(sb + ((c + 1) & 1) * STAGE_SZ, A, lda, B, ldb, (c + 1) << 6);
            cp_commit();
        }
        compute_chunk(sb + (c & 1) * STAGE_SZ, acc);
    }
}

#define EPI_COORDS                                     \
    const int lane = threadIdx.x & 31;                 \
    const int wid = threadIdx.x >> 5;                  \
    const int mw = (wid & 1) << 6;                     \
    const int nw = (wid >> 1) << 5;                    \
    const int r0 = lane >> 2;                          \
    const int c0 = (lane & 3) << 1;

// ---------------- narrow GEMM core: CTA 128x64, 8 warps 32x32, K-chunk 64 ----
#define STAGE64 27648                  // A 128*144 + B 64*144

__device__ __forceinline__ void issue_chunk64(uint32_t sb, const __half* A, int lda,
                                              const __half* B, int ldb, int k0) {
    const int t = threadIdx.x;
    #pragma unroll
    for (int i = 0; i < 4; ++i) {
        int v = t + (i << 8);
        int row = v >> 3, seg = v & 7;
        cpasync16(sb + row * ROWB + (seg << 4), A + (size_t)row * lda + k0 + (seg << 3));
    }
    #pragma unroll
    for (int i = 0; i < 2; ++i) {
        int v = t + (i << 8);
        int row = v >> 3, seg = v & 7;
        cpasync16(sb + SM_B_OFF + row * ROWB + (seg << 4),
                  B + (size_t)row * ldb + k0 + (seg << 3));
    }
}

__device__ __forceinline__ void compute_chunk64(uint32_t s, float acc[2][4][4]) {
    const int lane = threadIdx.x & 31, wid = threadIdx.x >> 5;
    const int m0w = (wid & 3) << 5;      // 0,32,64,96
    const int n0w = (wid >> 2) << 5;     // 0,32
    const int arow = lane & 15;
    const int khalf = (lane >> 4) << 3;
    #pragma unroll
    for (int s16 = 0; s16 < 64; s16 += 16) {
        const int coff = (s16 + khalf) * 2;
        uint32_t a[2][4], b[2][4];
        #pragma unroll
        for (int mi = 0; mi < 2; ++mi)
            ldsm4(a[mi], s + (m0w + mi * 16 + arow) * ROWB + coff);
        #pragma unroll
        for (int nj = 0; nj < 2; ++nj)
            ldsm4(b[nj], s + SM_B_OFF + (n0w + nj * 16 + arow) * ROWB + coff);
        #pragma unroll
        for (int mi = 0; mi < 2; ++mi)
            #pragma unroll
            for (int ni = 0; ni < 4; ++ni) {
                const int nj = ni >> 1, sel = ni & 1;
                mma16816(acc[mi][ni], a[mi], b[nj][sel], b[nj][sel + 2]);
            }
    }
}

__device__ __forceinline__ void gemm_run64(uint32_t sb, const __half* A, int lda,
                                           const __half* B, int ldb, int K,
                                           float acc[2][4][4]) {
    #pragma unroll
    for (int mi = 0; mi < 2; ++mi)
        #pragma unroll
        for (int ni = 0; ni < 4; ++ni)
            #pragma unroll
            for (int r = 0; r < 4; ++r) acc[mi][ni][r] = 0.f;

    const int nc = K >> 6;
    issue_chunk64(sb, A, lda, B, ldb, 0);
    cp_commit();
    for (int c = 0; c < nc; ++c) {
        cp_wait0();
        __syncthreads();
        if (c + 1 < nc) {
            issue_chunk64(sb + ((c + 1) & 1) * STAGE64, A, lda, B, ldb, (c + 1) << 6);
            cp_commit();
        }
        compute_chunk64(sb + (c & 1) * STAGE64, acc);
    }
}

#define EPI_COORDS64                                   \
    const int lane = threadIdx.x & 31;                 \
    const int wid = threadIdx.x >> 5;                  \
    const int mw = (wid & 3) << 5;                     \
    const int nw = (wid >> 2) << 5;                    \
    const int r0 = lane >> 2;                          \
    const int c0 = (lane & 3) << 1;

// ---------------- prep kernels ------------------------------------------------
__global__ void __launch_bounds__(256) conv_w_kernel(
        const float* __restrict__ wq, const float* __restrict__ wk,
        const float* __restrict__ wv, const float* __restrict__ wp) {
    int i = blockIdx.x * 256 + threadIdx.x;
    int which = i >> 16, j = i & 65535;
    const float* w = which == 0 ? wq : (which == 1 ? wk : (which == 2 ? wv : wp));
    g_w[i] = __float2half(w[j]);
}

__global__ void __launch_bounds__(256) gn_stats_kernel(const float* __restrict__ x) {
    if (threadIdx.x < 128) g_rsum[blockIdx.x * 128 + threadIdx.x] = 0.f;

    int b = blockIdx.x >> 5, g = blockIdx.x & 31;
    const size_t base = ((size_t)b * C + g * 8) * NPOS;
    const float4* xp = (const float4*)(x + base);
    const int NV = 8 * NPOS / 4;
    float s = 0.f, ss = 0.f;
    for (int i = threadIdx.x; i < NV; i += 256) {
        float4 v = xp[i];
        s  += v.x + v.y + v.z + v.w;
        ss += v.x * v.x + v.y * v.y + v.z * v.z + v.w * v.w;
    }
    #pragma unroll
    for (int o = 16; o; o >>= 1) {
        s  += __shfl_xor_sync(0xffffffffu, s, o);
        ss += __shfl_xor_sync(0xffffffffu, ss, o);
    }
    __shared__ float shs[8], shss[8];
    int w = threadIdx.x >> 5;
    if ((threadIdx.x & 31) == 0) { shs[w] = s; shss[w] = ss; }
    __syncthreads();
    if (threadIdx.x == 0) {
        float ts = 0.f, tss = 0.f;
        #pragma unroll
        for (int i = 0; i < 8; ++i) { ts += shs[i]; tss += shss[i]; }
        const float invN = 1.f / (8 * NPOS);
        float mean = ts * invN;
        float var = tss * invN - mean * mean;
        g_stats[blockIdx.x * 2]     = mean;
        g_stats[blockIdx.x * 2 + 1] = rsqrtf(var + 1e-6f);
    }
}

__global__ void gn_apply_kernel(const float* __restrict__ x,
                                const float* __restrict__ gamma,
                                const float* __restrict__ beta) {
    __shared__ float tile[32][33];
    int b = blockIdx.z, c0b = blockIdx.y * 32, n0b = blockIdx.x * 32;
    int tx = threadIdx.x, ty = threadIdx.y;
    #pragma unroll
    for (int i = 0; i < 4; ++i) {
        int cl = ty + i * 8;
        int c = c0b + cl;
        int g = c >> 3;
        float mean = g_stats[(b * 32 + g) * 2];
        float inv  = g_stats[(b * 32 + g) * 2 + 1];
        float gmul = gamma[c] * inv;
        float gadd = beta[c] - mean * gmul;
        float v = x[((size_t)b * C + c) * NPOS + n0b + tx];
        tile[cl][tx] = v * gmul + gadd;
    }
    __syncthreads();
    #pragma unroll
    for (int i = 0; i < 4; ++i) {
        int nl = ty + i * 8;
        size_t o = ((size_t)b * NPOS + n0b + nl) * C + c0b + tx;
        g_h[o] = __float2half(tile[tx][nl]);
    }
}

// ---------------- Q/K kernel (flattened grid, 256 CTAs) -----------------------
__global__ void __launch_bounds__(256, 2) qk_gemm(const float* __restrict__ bq,
                                                  const float* __restrict__ bk) {
    extern __shared__ char smem[];
    uint32_t sb = smem_u32(smem);
    int t = blockIdx.x;
    int which = t >> 7, r = t & 127;
    int b = r >> 6;
    int m0 = ((r & 63) >> 1) * 128;   // positions
    int n0 = (r & 1) * 128;           // out channels
    const __half* A = g_h + ((size_t)b * NPOS + m0) * C;
    const __half* B = g_w + (size_t)which * C * C + (size_t)n0 * C;
    float acc[4][4][4];
    gemm_run(sb, A, C, B, C, C, acc);

    const float* bias = which == 0 ? bq : bk;
    __half* out = which == 0 ? g_q : g_k;
    EPI_COORDS;
    #pragma unroll
    for (int ni = 0; ni < 4; ++ni) {
        int colg = n0 + nw + ni * 8 + c0;
        float bb0 = bias[colg], bb1 = bias[colg + 1];
        #pragma unroll
        for (int mi = 0; mi < 4; ++mi)
            #pragma unroll
            for (int rr = 0; rr < 2; ++rr) {
                int rowg = m0 + mw + mi * 16 + r0 + rr * 8;
                size_t off = ((size_t)b * NPOS + rowg) * C + colg;
                *reinterpret_cast<__half2*>(out + off) =
                    __floats2half2_rn(acc[mi][ni][rr * 2] + bb0,
                                      acc[mi][ni][rr * 2 + 1] + bb1);
            }
    }
}

// ---------------- V kernel (128 CTAs, channel-major out) ----------------------
__global__ void __launch_bounds__(256, 2) v_gemm(const float* __restrict__ bv) {
    extern __shared__ char smem[];
    uint32_t sb = smem_u32(smem);
    int r = blockIdx.x;
    int b = r >> 6;
    int m0 = ((r & 63) & 1) * 128;    // channels
    int n0 = ((r & 63) >> 1) * 128;   // positions
    const __half* A = g_w + (size_t)2 * C * C + (size_t)m0 * C;
    const __half* B = g_h + ((size_t)b * NPOS + n0) * C;
    float acc[4][4][4];
    gemm_run(sb, A, C, B, C, C, acc);

    EPI_COORDS;
    #pragma unroll
    for (int mi = 0; mi < 4; ++mi)
        #pragma unroll
        for (int rr = 0; rr < 2; ++rr) {
            int rowg = m0 + mw + mi * 16 + r0 + rr * 8;
            float bb = bv[rowg];
            #pragma unroll
            for (int ni = 0; ni < 4; ++ni) {
                int colg = n0 + nw + ni * 8 + c0;
                size_t off = (size_t)b * CN + (size_t)rowg * NPOS + colg;
                *reinterpret_cast<__half2*>(g_v + off) =
                    __floats2half2_rn(acc[mi][ni][rr * 2] + bb,
                                      acc[mi][ni][rr * 2 + 1] + bb);
            }
        }
}

// S+exp: P'[i,j] = exp(1/16 * Q[i,:].K[j,:]^T) fp16; row sums -> g_rsum.
__global__ void __launch_bounds__(256, 2) s_gemm() {
    extern __shared__ char smem[];
    uint32_t sb = smem_u32(smem);
    int b = blockIdx.z;
    int m0 = blockIdx.y * 128, n0 = blockIdx.x * 128;
    const __half* A = g_q + ((size_t)b * NPOS + m0) * C;
    const __half* B = g_k + ((size_t)b * NPOS + n0) * C;
    float acc[4][4][4];
    gemm_run(sb, A, C, B, C, C, acc);

    __shared__ float srows[128];
    if (threadIdx.x < 128) srows[threadIdx.x] = 0.f;
    __syncthreads();

    EPI_COORDS;
    __half* S = g_p + (size_t)b * SN;
    #pragma unroll
    for (int mi = 0; mi < 4; ++mi)
        #pragma unroll
        for (int rr = 0; rr < 2; ++rr) {
            int rowl = mw + mi * 16 + r0 + rr * 8;
            int rowg = m0 + rowl;
            float part = 0.f;
            #pragma unroll
            for (int ni = 0; ni < 4; ++ni) {
                int colg = n0 + nw + ni * 8 + c0;
                float e0 = __expf(acc[mi][ni][rr * 2] * 0.0625f);
                float e1 = __expf(acc[mi][ni][rr * 2 + 1] * 0.0625f);
                part += e0 + e1;
                *reinterpret_cast<__half2*>(S + (size_t)rowg * NPOS + colg) =
                    __floats2half2_rn(e0, e1);
            }
            part += __shfl_xor_sync(0xffffffffu, part, 1);
            part += __shfl_xor_sync(0xffffffffu, part, 2);
            if ((lane & 3) == 0) atomicAdd(&srows[rowl], part);
        }
    __syncthreads();
    if (threadIdx.x < 128)
        atomicAdd(&g_rsum[(size_t)b * NPOS + m0 + threadIdx.x], srows[threadIdx.x]);
}

// AV: O[i, c] = (P'[i,:] . V[c,:]^T) / rsum[i]  (K = 4096). CTA tile 128x64.
__global__ void __launch_bounds__(256, 2) av_gemm() {
    extern __shared__ char smem[];
    uint32_t sb = smem_u32(smem);
    int b = blockIdx.z;
    int m0 = blockIdx.y * 128, n0 = blockIdx.x * 64;
    const __half* A = g_p + (size_t)b * SN + (size_t)m0 * NPOS;
    const __half* B = g_v + (size_t)b * CN + (size_t)n0 * NPOS;
    float acc[2][4][4];
    gemm_run64(sb, A, NPOS, B, NPOS, NPOS, acc);

    EPI_COORDS64;
    #pragma unroll
    for (int mi = 0; mi < 2; ++mi)
        #pragma unroll
        for (int rr = 0; rr < 2; ++rr) {
            int rowg = m0 + mw + mi * 16 + r0 + rr * 8;
            float inv = 1.f / g_rsum[(size_t)b * NPOS + rowg];
            #pragma unroll
            for (int ni = 0; ni < 4; ++ni) {
                int colg = n0 + nw + ni * 8 + c0;
                size_t off = ((size_t)b * NPOS + rowg) * C + colg;
                *reinterpret_cast<__half2*>(g_o + off) =
                    __floats2half2_rn(acc[mi][ni][rr * 2] * inv,
                                      acc[mi][ni][rr * 2 + 1] * inv);
            }
        }
}

// proj: out[c, n] = x[c, n] + Wp[c,:] . O[n,:]^T + bp[c]. CTA tile 128x64.
__global__ void __launch_bounds__(256, 2) proj_gemm(const float* __restrict__ bp,
                                                    const float* __restrict__ x,
                                                    float* __restrict__ out) {
    extern __shared__ char smem[];
    uint32_t sb = smem_u32(smem);
    int b = blockIdx.z;
    int m0 = blockIdx.y * 128, n0 = blockIdx.x * 64;
    const __half* A = g_w + (size_t)3 * C * C + (size_t)m0 * C;
    const __half* B = g_o + ((size_t)b * NPOS + n0) * C;
    float acc[2][4][4];
    gemm_run64(sb, A, C, B, C, C, acc);

    EPI_COORDS64;
    #pragma unroll
    for (int mi = 0; mi < 2; ++mi)
        #pragma unroll
        for (int rr = 0; rr < 2; ++rr) {
            int rowg = m0 + mw + mi * 16 + r0 + rr * 8;
            float bb = bp[rowg];
            #pragma unroll
            for (int ni = 0; ni < 4; ++ni) {
                int colg = n0 + nw + ni * 8 + c0;
                size_t off = (size_t)b * CN + (size_t)rowg * NPOS + colg;
                float2 xv = *reinterpret_cast<const float2*>(x + off);
                float2 ov = make_float2(xv.x + acc[mi][ni][rr * 2] + bb,
                                        xv.y + acc[mi][ni][rr * 2 + 1] + bb);
                *reinterpret_cast<float2*>(out + off) = ov;
            }
        }
}

// ---------------- launch ------------------------------------------------------
extern "C" void kernel_launch(void* const* d_in, const int* in_sizes, int n_in,
                              void* d_out, int out_size) {
    const float* x  = (const float*)d_in[0];
    const float* gs = (const float*)d_in[1];
    const float* gb = (const float*)d_in[2];
    const float* wq = (const float*)d_in[3];
    const float* bq = (const float*)d_in[4];
    const float* wk = (const float*)d_in[5];
    const float* bk = (const float*)d_in[6];
    const float* wv = (const float*)d_in[7];
    const float* bv = (const float*)d_in[8];
    const float* wp = (const float*)d_in[9];
    const float* bp = (const float*)d_in[10];
    float* out = (float*)d_out;

    static bool init_done = false;
    static cudaStream_t s2;
    static cudaEvent_t evStart, evW, evH, evV;
    if (!init_done) {
        cudaFuncSetAttribute(qk_gemm,   cudaFuncAttributeMaxDynamicSharedMemorySize, SMEM_BYTES);
        cudaFuncSetAttribute(v_gemm,    cudaFuncAttributeMaxDynamicSharedMemorySize, SMEM_BYTES);
        cudaFuncSetAttribute(s_gemm,    cudaFuncAttributeMaxDynamicSharedMemorySize, SMEM_BYTES);
        cudaFuncSetAttribute(av_gemm,   cudaFuncAttributeMaxDynamicSharedMemorySize, 2 * STAGE64);
        cudaFuncSetAttribute(proj_gemm, cudaFuncAttributeMaxDynamicSharedMemorySize, 2 * STAGE64);
        cudaStreamCreateWithFlags(&s2, cudaStreamNonBlocking);
        cudaEventCreateWithFlags(&evStart, cudaEventDisableTiming);
        cudaEventCreateWithFlags(&evW,     cudaEventDisableTiming);
        cudaEventCreateWithFlags(&evH,     cudaEventDisableTiming);
        cudaEventCreateWithFlags(&evV,     cudaEventDisableTiming);
        init_done = true;
    }

    // fork: conv_w on side stream, concurrent with GN chain
    cudaEventRecord(evStart, 0);
    cudaStreamWaitEvent(s2, evStart, 0);
    conv_w_kernel<<<4 * C * C / 256, 256, 0, s2>>>(wq, wk, wv, wp);
    cudaEventRecord(evW, s2);

    gn_stats_kernel<<<BATCH * 32, 256>>>(x);
    gn_apply_kernel<<<dim3(NPOS / 32, C / 32, BATCH), dim3(32, 8)>>>(x, gs, gb);
    cudaEventRecord(evH, 0);

    // v on side stream, concurrent with qk + s
    cudaStreamWaitEvent(s2, evH, 0);
    v_gemm<<<128, 256, SMEM_BYTES, s2>>>(bv);
    cudaEventRecord(evV, s2);

    // main stream: qk needs g_w too
    cudaStreamWaitEvent(0, evW, 0);
    qk_gemm<<<256, 256, SMEM_BYTES>>>(bq, bk);
    s_gemm<<<dim3(NPOS / 128, NPOS / 128, BATCH), 256, SMEM_BYTES>>>();

    // join v before av
    cudaStreamWaitEvent(0, evV, 0);
    av_gemm<<<dim3(C / 64, NPOS / 128, BATCH), 256, 2 * STAGE64>>>();
    proj_gemm<<<dim3(NPOS / 64, C / 128, BATCH), 256, 2 * STAGE64>>>(bp, x, out);
}